// round 4
// baseline (speedup 1.0000x reference)
#include <cuda_runtime.h>

#define HID 50
#define JP  56          // padded hidden units (dead j 50..55)
#define K4N 13          // k padded 50->52, 4 per float4
#define BT  16          // batch rows per CTA
#define NTHREADS 448
#define HBUF_F4 (K4N * BT)   // 208 float4 per h buffer

typedef unsigned long long u64;

// Packed fp32x2 FMA (Blackwell), exact fp32 semantics per lane.
__device__ __forceinline__ void ffma2(u64& d, u64 a, u64 b) {
    asm("fma.rn.f32x2 %0, %1, %2, %3;" : "=l"(d) : "l"(a), "l"(b), "l"(d));
}
__device__ __forceinline__ float f2lo(u64 a) { return __uint_as_float((unsigned)a); }
__device__ __forceinline__ float f2hi(u64 a) { return __uint_as_float((unsigned)(a >> 32)); }

__device__ __forceinline__ float sigmoidf_(float x) {
    float e = __expf(-x);
    return __fdividef(1.f, 1.f + e);
}
__device__ __forceinline__ float tanhf_(float x) {
    float e = __expf(2.f * x);
    return 1.f - __fdividef(2.f, e + 1.f);
}

__global__ void __launch_bounds__(NTHREADS, 1)
seq2seq_kernel(const float* __restrict__ source,
               const float* __restrict__ eWih, const float* __restrict__ eWhh,
               const float* __restrict__ eBih, const float* __restrict__ eBhh,
               const float* __restrict__ dWih, const float* __restrict__ dWhh,
               const float* __restrict__ dBih, const float* __restrict__ dBhh,
               const float* __restrict__ fcW,  const float* __restrict__ fcB,
               float* __restrict__ out, int S, int T)
{
    extern __shared__ char smem_raw[];
    float4* wenc = (float4*)smem_raw;                 // [K4N][4 types][JP]
    float4* wdec = wenc + K4N * 4 * JP;
    float4* hbuf = wdec + K4N * 4 * JP;               // [2][K4N][BT]
    float*  xdec = (float*)(hbuf + 2 * HBUF_F4);      // [BT]
    float*  fcw  = xdec + BT;                         // [HID]
    float*  fcb  = fcw + HID;                         // [2]
    float*  srcs = fcb + 2;                           // [BT][S]

    const int tid  = threadIdx.x;
    const int lane = tid & 31;
    const int wrp  = tid >> 5;                        // [0,14)
    const int b0g  = blockIdx.x * BT;

    // thread = (hidden unit j, batch pair)
    const int half = wrp & 1;                         // batch half
    const int jg   = wrp >> 1;                        // [0,7): j-group of 8
    const int jl   = lane & 7;
    const int bp   = lane >> 3;                       // [0,4)
    const int j    = jg * 8 + jl;                     // [0,56)
    const int b0   = half * 8 + bp * 2;
    const int b1   = b0 + 1;

    // ---- stage weights: layout [k4][type][JP] float4 (k-values in the float4)
    for (int idx = tid; idx < K4N * 4 * JP; idx += NTHREADS) {
        int k4 = idx / (4 * JP);
        int r  = idx % (4 * JP);
        int ty = r / JP, jj = r % JP;
        float4 ve = make_float4(0.f, 0.f, 0.f, 0.f), vd = ve;
        if (jj < HID) {
            int row = ty * HID + jj;
            #pragma unroll
            for (int c = 0; c < 4; c++) {
                int k = 4 * k4 + c;
                if (k < HID) {
                    ((float*)&ve)[c] = eWhh[row * HID + k];
                    ((float*)&vd)[c] = dWhh[row * HID + k];
                }
            }
        }
        wenc[idx] = ve;
        wdec[idx] = vd;
    }
    for (int i = tid; i < 2 * HBUF_F4; i += NTHREADS)
        hbuf[i] = make_float4(0.f, 0.f, 0.f, 0.f);
    if (tid < BT)  xdec[tid] = 0.f;
    if (tid < HID) fcw[tid] = fcW[tid];
    if (tid == 0)  fcb[0] = fcB[0];
    for (int bl = 0; bl < BT; bl++)
        for (int t = tid; t < S; t += NTHREADS)
            srcs[bl * S + t] = source[(size_t)(b0g + bl) * S + t];

    // ---- per-thread constants / state
    float biasr[4], wihr[4];
    #pragma unroll
    for (int ty = 0; ty < 4; ty++) {
        if (j < HID) {
            int row = ty * HID + j;
            biasr[ty] = eBih[row] + eBhh[row];
            wihr[ty]  = eWih[row];
        } else { biasr[ty] = 0.f; wihr[ty] = 0.f; }
    }
    float c0 = 0.f, c1 = 0.f;
    __syncthreads();

    const ulonglong2* wenc2 = (const ulonglong2*)wenc;
    const ulonglong2* wdec2 = (const ulonglong2*)wdec;

    float g[8];  // [type][bi] gate pre-activations

    auto gemm = [&](const ulonglong2* w2, const ulonglong2* hb2, float x0v, float x1v) {
        u64 a[8];
        #pragma unroll
        for (int ty = 0; ty < 4; ty++) {
            a[2 * ty]     = (u64)__float_as_uint(fmaf(x0v, wihr[ty], biasr[ty]));
            a[2 * ty + 1] = (u64)__float_as_uint(fmaf(x1v, wihr[ty], biasr[ty]));
        }
        #pragma unroll
        for (int k4 = 0; k4 < K4N; k4++) {
            ulonglong2 hv0 = hb2[k4 * BT + b0];     // 4 distinct 16B: 1 wavefront
            ulonglong2 hv1 = hb2[k4 * BT + b1];
            #pragma unroll
            for (int ty = 0; ty < 4; ty++) {
                ulonglong2 wv = w2[(k4 * 4 + ty) * JP + j];  // 8 consecutive 16B: dense 128B
                ffma2(a[2 * ty],     wv.x, hv0.x);
                ffma2(a[2 * ty],     wv.y, hv0.y);
                ffma2(a[2 * ty + 1], wv.x, hv1.x);
                ffma2(a[2 * ty + 1], wv.y, hv1.y);
            }
        }
        #pragma unroll
        for (int i = 0; i < 8; i++) g[i] = f2lo(a[i]) + f2hi(a[i]);
    };

    // in-thread LSTM update: gates never leave registers
    auto update = [&](float* hnext) {
        {   // batch row b0
            float iv = sigmoidf_(g[0]);
            float fv = sigmoidf_(g[2]);
            float gv = tanhf_(g[4]);
            float ov = sigmoidf_(g[6]);
            c0 = fmaf(fv, c0, iv * gv);
            float h = ov * tanhf_(c0);
            if (j < 4 * K4N) hnext[(j >> 2) * (BT * 4) + b0 * 4 + (j & 3)] = h;
        }
        {   // batch row b1
            float iv = sigmoidf_(g[1]);
            float fv = sigmoidf_(g[3]);
            float gv = tanhf_(g[5]);
            float ov = sigmoidf_(g[7]);
            c1 = fmaf(fv, c1, iv * gv);
            float h = ov * tanhf_(c1);
            if (j < 4 * K4N) hnext[(j >> 2) * (BT * 4) + b1 * 4 + (j & 3)] = h;
        }
    };

    // gate order in accumulators: a[2ty+bi], ty: 0=i,1=f,2=g,3=o
    // (g[] indexing above: g[0]=i/b0, g[1]=i/b1, g[2]=f/b0, ... matches 2*ty+bi)

    int pb = 0;

    // ================= encoder =================
    for (int t = 0; t < S; t++) {
        const ulonglong2* cur = (const ulonglong2*)(hbuf + pb * HBUF_F4);
        float* nxt = (float*)(hbuf + (pb ^ 1) * HBUF_F4);
        float x0v = srcs[b0 * S + t];
        float x1v = srcs[b1 * S + t];
        gemm(wenc2, cur, x0v, x1v);
        update(nxt);
        pb ^= 1;
        __syncthreads();
    }

    // ================= decoder =================
    #pragma unroll
    for (int ty = 0; ty < 4; ty++) {
        if (j < HID) {
            int row = ty * HID + j;
            biasr[ty] = dBih[row] + dBhh[row];
            wihr[ty]  = dWih[row];
        } else { biasr[ty] = 0.f; wihr[ty] = 0.f; }
    }

    for (int t = 0; t < T; t++) {
        const ulonglong2* cur = (const ulonglong2*)(hbuf + pb * HBUF_F4);
        float* nxt = (float*)(hbuf + (pb ^ 1) * HBUF_F4);
        float x0v = xdec[b0];
        float x1v = xdec[b1];
        gemm(wdec2, cur, x0v, x1v);
        update(nxt);
        pb ^= 1;
        __syncthreads();                      // h_t visible

        if (wrp == 0) {                       // fc on h_t (buffer pb)
            const float* hf = (const float*)(hbuf + pb * HBUF_F4);
            const int bfc = lane & 15;
            const int hhf = lane >> 4;
            float s = 0.f;
            #pragma unroll
            for (int jj2 = 0; jj2 < 25; jj2++) {
                int jq = hhf * 25 + jj2;
                s = fmaf(hf[(jq >> 2) * (BT * 4) + bfc * 4 + (jq & 3)], fcw[jq], s);
            }
            s += __shfl_xor_sync(0xffffffffu, s, 16);
            if (hhf == 0) {
                float y = s + fcb[0];
                xdec[bfc] = y;
                out[(size_t)(b0g + bfc) * T + t] = y;
            }
        }
        __syncthreads();                      // xdec ready for next step
    }
}

extern "C" void kernel_launch(void* const* d_in, const int* in_sizes, int n_in,
                              void* d_out, int out_size)
{
    const float* source = (const float*)d_in[0];
    const float* eWih = (const float*)d_in[1];
    const float* eWhh = (const float*)d_in[2];
    const float* eBih = (const float*)d_in[3];
    const float* eBhh = (const float*)d_in[4];
    const float* dWih = (const float*)d_in[5];
    const float* dWhh = (const float*)d_in[6];
    const float* dBih = (const float*)d_in[7];
    const float* dBhh = (const float*)d_in[8];
    const float* fcW  = (const float*)d_in[9];
    const float* fcB  = (const float*)d_in[10];
    float* out = (float*)d_out;

    const int B = 2048;
    const int S = in_sizes[0] / B;   // 512
    const int T = out_size   / B;    // 256

    size_t sm = sizeof(float4) * (size_t)(K4N * 4 * JP * 2 + 2 * HBUF_F4)
              + sizeof(float)  * (size_t)(BT + HID + 2)
              + sizeof(float)  * (size_t)BT * S;

    cudaFuncSetAttribute(seq2seq_kernel, cudaFuncAttributeMaxDynamicSharedMemorySize, (int)sm);
    seq2seq_kernel<<<B / BT, NTHREADS, sm>>>(source, eWih, eWhh, eBih, eBhh,
                                             dWih, dWhh, dBih, dBhh, fcW, fcB,
                                             out, S, T);
}